// round 17
// baseline (speedup 1.0000x reference)
#include <cuda_runtime.h>
#include <cstdint>
#include <cstddef>

// DifferentiableBundleAdjustment, round 4 (resubmit; R13-R16 never ran).
// R12 evidence: traffic still 358MB (read amplification to full 128B lines is
// fetch-policy, NOT spills), BW 5.2TB/s capped by per-warp outstanding
// cp.async (~28KB/warp x 128 warps = 3.6MB in flight). Fix: 4x the warps.
// 512 warps x 8 chain-rows each; every warp self-contained (own cp.async
// ring, own output stage, warp-local __syncwarp only). All 32 lanes run the
// chain redundantly for row (lane&7); lanes 0-7 store. Ring deepened to 16.

constexpr int B_DIM = 4096;
constexpr int S_DIM = 512;
constexpr int PD    = 32;    // dba_params last dim
constexpr int SD    = 15;    // output last dim
constexpr int UB    = 8;     // steps per body
constexpr int NBODY = S_DIM / UB;    // 64
constexpr int RPW   = 8;     // chain rows per warp
constexpr int WARPS = 4;     // warps per block
constexpr int RING  = 16;    // cp.async ring depth (power of 2)
constexpr int DROW  = 68;    // floats per row per stage (64 data + 4 pad; 272B)
constexpr int DSTAGE = RPW * DROW;          // 544 floats per stage
constexpr int ROW_F  = 132;  // out-stage floats per row (528B)
constexpr int OSTG_F = RPW * ROW_F;         // 1056 floats
constexpr int WSPAN  = RING * DSTAGE + OSTG_F;      // floats per warp = 9760
constexpr int SMEM_BYTES = WARPS * WSPAN * 4;       // 156160 B

__device__ __forceinline__ void cpa16(uint32_t dst, const float* src) {
    asm volatile("cp.async.cg.shared.global [%0], [%1], 16;\n"
                 :: "r"(dst), "l"(src));
}
#define CPA_COMMIT() asm volatile("cp.async.commit_group;\n" ::: "memory")
#define CPA_WAIT15() asm volatile("cp.async.wait_group 15;\n" ::: "memory")

// Issue one body's deltas into this warp's ring stage (kb % RING).
// Tasks: 8 rows x 8 steps x 2 halves of 16B = 128 -> 4 warp instructions.
// Instr i: lanes 0-15 -> row 2i, lanes 16-31 -> row 2i+1; piece = lane&15
// selects step j = piece>>1 and 16B half = piece&1. SMEM packs 64 floats/row.
#define ISSUE(kb)                                                              \
    {                                                                          \
        uint32_t dstage = sbase + (uint32_t)(((kb) & (RING - 1)) * (DSTAGE * 4)); \
        const float* srcb = dba_w + (size_t)(kb) * (UB * PD);                  \
        _Pragma("unroll")                                                      \
        for (int i = 0; i < 4; i++) {                                          \
            int r = 2 * i + half;                                              \
            cpa16(dstage + (uint32_t)(r * (DROW * 4) + piece * 16),            \
                  srcb + (size_t)r * (S_DIM * PD)                              \
                       + (piece >> 1) * PD + (piece & 1) * 4);                 \
        }                                                                      \
    }

// Store the 7 state floats at float-offset 15*j from the 16B-aligned row
// base; ph = (3*j) & 3. Never touches the pre-zeroed tail [7..15) of the row.
__device__ __forceinline__ void put7(float* o, int ph,
                                     float p0, float p1, float p2,
                                     float q0, float q1, float q2, float q3)
{
    if (ph == 0) {
        *reinterpret_cast<float4*>(o + 0) = make_float4(p0, p1, p2, q0);
        *reinterpret_cast<float2*>(o + 4) = make_float2(q1, q2);
        o[6] = q3;
    } else if (ph == 1) {
        o[0] = p0;
        *reinterpret_cast<float2*>(o + 1) = make_float2(p1, p2);
        *reinterpret_cast<float4*>(o + 3) = make_float4(q0, q1, q2, q3);
    } else if (ph == 2) {
        *reinterpret_cast<float2*>(o + 0) = make_float2(p0, p1);
        *reinterpret_cast<float4*>(o + 2) = make_float4(p2, q0, q1, q2);
        o[6] = q3;
    } else {
        o[0] = p0;
        *reinterpret_cast<float4*>(o + 1) = make_float4(p1, p2, q0, q1);
        *reinterpret_cast<float2*>(o + 5) = make_float2(q2, q3);
    }
}

// Coalesced copy-out: 8 rows x 480B (8 steps x 15 floats incl. zeros).
// Lanes 0-29 move 16B per row; both sides 16B-aligned (480B chunk multiples).
#define COPYOUT(k)                                                             \
    if (lane < 30) {                                                           \
        float* od = ob + (size_t)(k) * (UB * SD);                              \
        const int cofs = 4 * lane;                                             \
        _Pragma("unroll")                                                      \
        for (int r = 0; r < RPW; r++) {                                        \
            float4 v = *reinterpret_cast<const float4*>(ostage + r * ROW_F + cofs); \
            *reinterpret_cast<float4*>(od + (size_t)r * (S_DIM * SD) + cofs) = v;   \
        }                                                                      \
    }

__global__ void __launch_bounds__(WARPS * 32, 1)
dba_scan_kernel(const float* __restrict__ dba,
                const float* __restrict__ gt,
                float* __restrict__ out)
{
    extern __shared__ float smem[];

    const int tid  = threadIdx.x;
    const int lane = tid & 31;
    const int wid  = tid >> 5;
    const int half  = lane >> 4;   // cp.async row parity
    const int piece = lane & 15;   // cp.async 16B piece
    const int crow  = lane & 7;    // chain row this lane computes (redundant x4)

    float* wbase  = smem + wid * WSPAN;
    float* dring  = wbase;                  // RING * DSTAGE floats
    float* ostage = wbase + RING * DSTAGE;  // OSTG_F floats

    const int rowbase = blockIdx.x * (WARPS * RPW) + wid * RPW;

    const float* __restrict__ dba_w = dba + (size_t)rowbase * S_DIM * PD;
    const float* __restrict__ g =
        gt + (size_t)(rowbase + crow) * S_DIM * SD;   // row s=0, in-bounds for all lanes
    float* __restrict__ ob = out + (size_t)rowbase * S_DIM * SD;

    const uint32_t sbase = (uint32_t)__cvta_generic_to_shared(dring);

    // Zero-prefill the out stage once; put7 never touches the zero tails.
    for (int i = lane; i < OSTG_F; i += 32) ostage[i] = 0.f;

    // Initial state (g[0..6]; g base 16B-aligned: idx*15*512*4 % 16 == 0).
    float4 ga = *reinterpret_cast<const float4*>(g + 0);
    float4 gb = *reinterpret_cast<const float4*>(g + 4);
    float p0 = ga.x, p1 = ga.y, p2 = ga.z;
    float q0 = ga.w, q1 = gb.x, q2 = gb.y, q3 = gb.z;

    // Prologue: issue bodies 0..RING-2 (15 groups in flight).
    #pragma unroll 1
    for (int s = 0; s < RING - 1; s++) {
        ISSUE(s);
        CPA_COMMIT();
    }
    __syncwarp();   // ostage zero-fill visible across the warp

    float* const srow = ostage + crow * ROW_F;

    #pragma unroll 1
    for (int k = 0; k < NBODY; k++) {
        // Keep 15 groups pending: issue k+RING-1 (empty commits at the tail
        // keep the count constant so wait_group(15) completes exactly body k).
        int kb = k + RING - 1;
        if (kb < NBODY) { ISSUE(kb); }
        CPA_COMMIT();
        CPA_WAIT15();
        __syncwarp();   // cross-lane visibility of this stage's data

        const float* drow = dring + (k & (RING - 1)) * DSTAGE + crow * DROW;

        #pragma unroll
        for (int j = 0; j < UB; j++) {
            if (lane < RPW)
                put7(srow + j * SD, (3 * j) & 3, p0, p1, p2, q0, q1, q2, q3);
            float4 da = *reinterpret_cast<const float4*>(drow + j * 8);
            float4 db = *reinterpret_cast<const float4*>(drow + j * 8 + 4);
            p0 = fmaf(0.1f, da.x, p0);
            p1 = fmaf(0.1f, da.y, p1);
            p2 = fmaf(0.1f, da.z, p2);
            float u0 = fmaf(0.1f, da.w, q0);
            float u1 = fmaf(0.1f, db.x, q1);
            float u2 = fmaf(0.1f, db.y, q2);
            float u3 = fmaf(0.1f, db.z, q3);
            float nrm = fmaf(u0, u0, u1 * u1) + fmaf(u2, u2, u3 * u3);
            float r = rsqrtf(nrm);
            q0 = u0 * r; q1 = u1 * r; q2 = u2 * r; q3 = u3 * r;
        }

        __syncwarp();   // staged state visible to copy lanes
        COPYOUT(k);
        __syncwarp();   // copy done before next body's put7 overwrites stage
    }
}

extern "C" void kernel_launch(void* const* d_in, const int* in_sizes, int n_in,
                              void* d_out, int out_size)
{
    const float* dba = (const float*)d_in[0];   // [4096, 512, 32]
    // d_in[1] = imu_measurements: unused by the reference computation
    const float* gt  = (const float*)d_in[2];   // [4096, 512, 15]
    float* out = (float*)d_out;                 // [4096, 512, 15]

    (void)in_sizes; (void)n_in; (void)out_size;

    // Unconditional (no static guard — harness rule): host-side, idempotent,
    // not a stream op, so graph-capture-safe.
    cudaFuncSetAttribute(dba_scan_kernel,
                         cudaFuncAttributeMaxDynamicSharedMemorySize,
                         SMEM_BYTES);

    dba_scan_kernel<<<B_DIM / (WARPS * RPW), WARPS * 32, SMEM_BYTES>>>(dba, gt, out);
}